// round 3
// baseline (speedup 1.0000x reference)
#include <cuda_runtime.h>
#include <math.h>
#include <stdint.h>

#define N_PTS 65536
#define DIMS  64
#define KCL   128
#define ABLK  128                 // points per assign/scatter block
#define NBLK  (N_PTS / ABLK)      // 512
#define KD    (KCL * DIMS)        // 8192
#define EPSV  1e-8f
#define BIGF  3.402823466e38f

// ----------------------------------------------------------------------------
// Device scratch (static, no allocation)
// ----------------------------------------------------------------------------
__device__ int    g_pred[N_PTS];
__device__ int    g_histx[NBLK * KCL];
__device__ int    g_histt[NBLK * KCL];
__device__ float  g_fill[KCL];
__device__ int    g_m[KCL];
__device__ int    g_P[KCL];
__device__ int    g_off[KCL];
__device__ double g_loss[2];   // [0] = loss_fil, [1] = loss_med
__device__ float  g_xg[(size_t)(2 * N_PTS) * DIMS];
__device__ float  g_tg[(size_t)(2 * N_PTS) * DIMS];

// ----------------------------------------------------------------------------
// K0: zero accumulators
// ----------------------------------------------------------------------------
__global__ void k_init() {
    int t = threadIdx.x;
    if (t < KCL) g_fill[t] = 0.0f;
    if (t < 2)   g_loss[t] = 0.0;
}

// ----------------------------------------------------------------------------
// K1: distances to 128 centers, argmin, soft filling (single distance pass via
//     shared w-cache), and per-block histograms for BOTH x-pred and t-pred.
// ----------------------------------------------------------------------------
__global__ void k_assign(const float* __restrict__ x, const float* __restrict__ cc,
                         const int* __restrict__ predt) {
    extern __shared__ float dyn[];
    float* sc    = dyn;                      // 8192 floats
    float* scn   = sc + KCL * DIMS;          // 128
    float* wca   = scn + KCL;                // KCL*ABLK = 16384
    float* sfill = wca + KCL * ABLK;         // 128
    int*   shx   = (int*)(sfill + KCL);      // 128
    int*   sht   = shx + KCL;                // 128

    const int tid = threadIdx.x;

    for (int j = tid; j < KCL * DIMS; j += ABLK) sc[j] = cc[j];
    if (tid < KCL) { sfill[tid] = 0.0f; shx[tid] = 0; sht[tid] = 0; }
    __syncthreads();
    if (tid < KCL) {
        float s = 0.0f;
        const float* cp = sc + tid * DIMS;
        #pragma unroll
        for (int d = 0; d < DIMS; d++) s += cp[d] * cp[d];
        scn[tid] = s;
    }
    __syncthreads();

    const int i = blockIdx.x * ABLK + tid;
    float xr[DIMS];
    {
        const float4* xp = (const float4*)(x + (size_t)i * DIMS);
        #pragma unroll
        for (int q = 0; q < 16; q++) {
            float4 v = xp[q];
            xr[4*q] = v.x; xr[4*q+1] = v.y; xr[4*q+2] = v.z; xr[4*q+3] = v.w;
        }
    }
    float xn = 0.0f;
    #pragma unroll
    for (int d = 0; d < DIMS; d++) xn += xr[d] * xr[d];

    // single distance pass: cache w, accumulate wsum, track argmin
    float wsum = 0.0f, best = BIGF;
    int bc = 0;
    for (int c = 0; c < KCL; c++) {
        const float4* cp = (const float4*)(sc + c * DIMS);
        float a0 = 0.f, a1 = 0.f, a2 = 0.f, a3 = 0.f;
        #pragma unroll
        for (int q = 0; q < 16; q++) {
            float4 v = cp[q];
            a0 += xr[4*q]   * v.x;
            a1 += xr[4*q+1] * v.y;
            a2 += xr[4*q+2] * v.z;
            a3 += xr[4*q+3] * v.w;
        }
        float dot = (a0 + a1) + (a2 + a3);
        float d2 = xn + scn[c] - 2.0f * dot;
        float dist = sqrtf(fmaxf(d2, 0.0f));
        if (dist < best) { best = dist; bc = c; }
        float w = __fdividef(1.0f, dist + EPSV);
        wca[c * ABLK + tid] = w;
        wsum += w;
    }
    const float inv = __fdividef(1.0f, wsum);
    const int lane = tid & 31;

    // pass 2: normalized weights from cache -> per-cluster fill
    for (int c = 0; c < KCL; c++) {
        float w = wca[c * ABLK + tid] * inv;
        #pragma unroll
        for (int o = 16; o > 0; o >>= 1) w += __shfl_down_sync(0xffffffffu, w, o);
        if (lane == 0) atomicAdd(&sfill[c], w);
    }

    g_pred[i] = bc;
    atomicAdd(&shx[bc], 1);
    atomicAdd(&sht[predt[i]], 1);
    __syncthreads();
    if (tid < KCL) {
        atomicAdd(&g_fill[tid], sfill[tid]);
        g_histx[blockIdx.x * KCL + tid] = shx[tid];
        g_histt[blockIdx.x * KCL + tid] = sht[tid];
    }
}

// ----------------------------------------------------------------------------
// K2a: parallel exclusive scan of the 512-entry histogram column per cluster.
// ----------------------------------------------------------------------------
__global__ void k_scan1() {
    const int c = blockIdx.x;
    const int t = threadIdx.x;
    __shared__ int s[NBLK];

    // ---- x hist ----
    int v = g_histx[t * KCL + c];
    s[t] = v; __syncthreads();
    int acc = v;
    for (int o = 1; o < NBLK; o <<= 1) {
        int add = (t >= o) ? s[t - o] : 0;
        __syncthreads();
        acc += add; s[t] = acc;
        __syncthreads();
    }
    g_histx[t * KCL + c] = acc - v;          // exclusive
    int cntx = s[NBLK - 1];
    __syncthreads();

    // ---- t hist ----
    v = g_histt[t * KCL + c];
    s[t] = v; __syncthreads();
    acc = v;
    for (int o = 1; o < NBLK; o <<= 1) {
        int add = (t >= o) ? s[t - o] : 0;
        __syncthreads();
        acc += add; s[t] = acc;
        __syncthreads();
    }
    g_histt[t * KCL + c] = acc - v;
    int cntt = s[NBLK - 1];

    if (t == 0) {
        int m = min(cntx, cntt);
        g_m[c] = m;
        int P = 0;
        if (m > 0) { P = 1; while (P < m) P <<= 1; }
        g_P[c] = P;
    }
}

// ----------------------------------------------------------------------------
// K2b: offsets across clusters + loss_fil. Single block of 128.
// ----------------------------------------------------------------------------
__global__ void k_scan2(const float* __restrict__ ftgt) {
    const int c = threadIdx.x;
    __shared__ int sp[KCL];
    __shared__ float sd[KCL];
    sp[c] = g_P[c];
    float diff = g_fill[c] * (1.0f / N_PTS) - ftgt[c];
    sd[c] = diff * diff;
    __syncthreads();
    if (c == 0) {
        int acc = 0;
        for (int k = 0; k < KCL; k++) { g_off[k] = acc; acc += sp[k]; }
        float s = 0.0f;
        for (int k = 0; k < KCL; k++) s += sd[k];
        g_loss[0] = (double)(s / KCL);
    }
}

// ----------------------------------------------------------------------------
// K3: stable rank within cluster + gather first-m rows, feature-major padded.
// ----------------------------------------------------------------------------
__global__ void k_scatter(const float* __restrict__ src,
                          const int* __restrict__ predt, int side) {
    __shared__ int cnt[KCL];
    const int tid = threadIdx.x;
    if (tid < KCL) cnt[tid] = 0;
    __syncthreads();

    const int i = blockIdx.x * ABLK + tid;
    const int c = side ? predt[i] : g_pred[i];
    const int myw = tid >> 5, lane = tid & 31;
    int lrank = 0;

    for (int w = 0; w < ABLK / 32; w++) {
        if (myw == w) {
            unsigned peers = __match_any_sync(0xffffffffu, c);
            unsigned lower = peers & ((1u << lane) - 1u);
            int leader = __ffs(peers) - 1;
            int base = 0;
            if (lane == leader) base = atomicAdd(&cnt[c], __popc(peers));
            base = __shfl_sync(0xffffffffu, base, leader);
            lrank = base + __popc(lower);
        }
        __syncthreads();
    }

    const int* hist = side ? g_histt : g_histx;
    const int r = hist[blockIdx.x * KCL + c] + lrank;
    const int m = g_m[c];
    if (r < m) {
        const int P = g_P[c];
        float* dst = (side ? g_tg : g_xg) + (size_t)g_off[c] * DIMS + r;
        const float4* sp = (const float4*)(src + (size_t)i * DIMS);
        #pragma unroll
        for (int q = 0; q < 16; q++) {
            float4 v = sp[q];
            dst[(size_t)(4*q)     * P] = v.x;
            dst[(size_t)(4*q + 1) * P] = v.y;
            dst[(size_t)(4*q + 2) * P] = v.z;
            dst[(size_t)(4*q + 3) * P] = v.w;
        }
    }
}

// ----------------------------------------------------------------------------
// K4: register/shfl-blocked bitonic sort, CHUNKED register phases.
//     Strides j<=16 exchange only within a w-slice (partner idx^j has the same
//     w), so w-slices are processed independently in chunks of VC values ->
//     bounded register pressure at any thread count.
// ----------------------------------------------------------------------------
template<int TT, int VC>
__global__ void __launch_bounds__(TT)
k_sort_reg(int lo, int hi) {
    const int s = blockIdx.x;
    float* buf = (s < KD) ? g_xg : g_tg;
    const int cd = (s < KD) ? s : s - KD;
    const int c = cd >> 6, d = cd & 63;
    const int m = g_m[c];
    if (m < 2) return;
    const int P = g_P[c];
    if (P <= lo || P > hi) return;

    extern __shared__ float sh[];
    float* seg = buf + (size_t)g_off[c] * DIMS + (size_t)d * P;
    const int tid = threadIdx.x;

    for (int idx = tid; idx < P; idx += TT)
        sh[idx] = (idx < m) ? seg[idx] : BIGF;
    __syncthreads();

    // phase 1: k = 2 .. min(32, P) entirely in registers, chunk by chunk
    const int kmax1 = (P < 32) ? P : 32;
    for (int base = 0; base < P; base += TT * VC) {
        float v[VC];
        #pragma unroll
        for (int w = 0; w < VC; w++) {
            int idx = base + w * TT + tid;
            v[w] = (idx < P) ? sh[idx] : BIGF;
        }
        for (int k = 2; k <= kmax1; k <<= 1) {
            for (int j = k >> 1; j > 0; j >>= 1) {
                #pragma unroll
                for (int w = 0; w < VC; w++) {
                    int idx = base + w * TT + tid;
                    float pv = __shfl_xor_sync(0xffffffffu, v[w], j);
                    bool desc  = (idx & k) != 0;
                    bool upper = (idx & j) != 0;
                    v[w] = (upper != desc) ? fmaxf(v[w], pv) : fminf(v[w], pv);
                }
            }
        }
        #pragma unroll
        for (int w = 0; w < VC; w++) {
            int idx = base + w * TT + tid;
            if (idx < P) sh[idx] = v[w];
        }
    }
    __syncthreads();

    // phase 2: k = 64 .. P; strides >=32 via shared, <=16 via registers
    for (int k = 64; k <= P; k <<= 1) {
        for (int j = k >> 1; j >= 32; j >>= 1) {
            for (int idx = tid; idx < P; idx += TT) {
                int l = idx ^ j;
                if (l > idx) {
                    float a = sh[idx], b = sh[l];
                    bool up = ((idx & k) == 0);
                    if ((a > b) == up) { sh[idx] = b; sh[l] = a; }
                }
            }
            __syncthreads();
        }
        for (int base = 0; base < P; base += TT * VC) {
            float v[VC];
            #pragma unroll
            for (int w = 0; w < VC; w++) {
                int idx = base + w * TT + tid;
                v[w] = (idx < P) ? sh[idx] : BIGF;
            }
            for (int j = 16; j > 0; j >>= 1) {
                #pragma unroll
                for (int w = 0; w < VC; w++) {
                    int idx = base + w * TT + tid;
                    float pv = __shfl_xor_sync(0xffffffffu, v[w], j);
                    bool desc  = (idx & k) != 0;
                    bool upper = (idx & j) != 0;
                    v[w] = (upper != desc) ? fmaxf(v[w], pv) : fminf(v[w], pv);
                }
            }
            #pragma unroll
            for (int w = 0; w < VC; w++) {
                int idx = base + w * TT + tid;
                if (idx < P) sh[idx] = v[w];
            }
        }
        __syncthreads();
    }

    for (int idx = tid; idx < m; idx += TT) seg[idx] = sh[idx];
}

// Fallback: global-memory bitonic for P > 32768 (degenerate giant cluster)
__global__ void __launch_bounds__(1024)
k_sort_global(int lo) {
    const int s = blockIdx.x;
    float* buf = (s < KD) ? g_xg : g_tg;
    const int cd = (s < KD) ? s : s - KD;
    const int c = cd >> 6, d = cd & 63;
    const int m = g_m[c];
    if (m < 2) return;
    const int P = g_P[c];
    if (P <= lo) return;

    float* seg = buf + (size_t)g_off[c] * DIMS + (size_t)d * P;
    const int T = blockDim.x, tid = threadIdx.x;
    for (int j = m + tid; j < P; j += T) seg[j] = BIGF;
    __syncthreads();

    for (int k = 2; k <= P; k <<= 1) {
        for (int j = k >> 1; j > 0; j >>= 1) {
            for (int idx = tid; idx < P; idx += T) {
                int l = idx ^ j;
                if (l > idx) {
                    float a = seg[idx], b = seg[l];
                    bool up = ((idx & k) == 0);
                    if ((a > b) == up) { seg[idx] = b; seg[l] = a; }
                }
            }
            __syncthreads();
        }
    }
}

// ----------------------------------------------------------------------------
// K5: Wasserstein sums
// ----------------------------------------------------------------------------
__global__ void k_diff() {
    const int cd = blockIdx.x;
    const int c = cd >> 6, d = cd & 63;
    const int m = g_m[c];
    if (m < 1) return;
    const int P = g_P[c];
    const size_t base = (size_t)g_off[c] * DIMS + (size_t)d * P;

    float s = 0.0f;
    for (int j = threadIdx.x; j < m; j += blockDim.x)
        s += fabsf(g_xg[base + j] - g_tg[base + j]);

    __shared__ float red[256];
    red[threadIdx.x] = s;
    __syncthreads();
    for (int o = blockDim.x >> 1; o > 0; o >>= 1) {
        if (threadIdx.x < o) red[threadIdx.x] += red[threadIdx.x + o];
        __syncthreads();
    }
    if (threadIdx.x == 0)
        atomicAdd(&g_loss[1], (double)red[0] / ((double)m * DIMS));
}

// ----------------------------------------------------------------------------
// K6: finalize
// ----------------------------------------------------------------------------
__global__ void k_final(float* out) {
    out[0] = (float)(g_loss[0] + g_loss[1]);
}

// ----------------------------------------------------------------------------
// Launch
// ----------------------------------------------------------------------------
extern "C" void kernel_launch(void* const* d_in, const int* in_sizes, int n_in,
                              void* d_out, int out_size) {
    const float* x     = (const float*)d_in[0];
    const float* tgt   = (const float*)d_in[1];
    const float* cc    = (const float*)d_in[2];
    const int*   predt = (const int*)d_in[3];
    const float* ftgt  = (const float*)d_in[4];
    float* out = (float*)d_out;

    const int ASSIGN_SMEM = (KCL * DIMS + KCL + KCL * ABLK + KCL) * 4 + KCL * 8;
    cudaFuncSetAttribute(k_assign,
                         cudaFuncAttributeMaxDynamicSharedMemorySize, ASSIGN_SMEM);
    cudaFuncSetAttribute(k_sort_reg<1024, 8>,
                         cudaFuncAttributeMaxDynamicSharedMemorySize, 131072);

    k_init<<<1, 128>>>();
    k_assign<<<NBLK, ABLK, ASSIGN_SMEM>>>(x, cc, predt);
    k_scan1<<<KCL, NBLK>>>();
    k_scan2<<<1, KCL>>>(ftgt);
    k_scatter<<<NBLK, ABLK>>>(x, predt, 0);
    k_scatter<<<NBLK, ABLK>>>(tgt, predt, 1);
    // sort tiers: P in (1, 2048] regs+8KB smem; (2048, 32768] regs+128KB smem;
    // > 32768 global-memory fallback.
    k_sort_reg<256, 8><<<2 * KD, 256, 2048 * sizeof(float)>>>(1, 2048);
    k_sort_reg<1024, 8><<<2 * KD, 1024, 32768 * sizeof(float)>>>(2048, 32768);
    k_sort_global<<<2 * KD, 1024>>>(32768);
    k_diff<<<KD, 256>>>();
    k_final<<<1, 1>>>(out);
}